// round 4
// baseline (speedup 1.0000x reference)
#include <cuda_runtime.h>
#include <cuda_bf16.h>
#include <math.h>
#include <stdint.h>

// Problem constants
#define Bn    4
#define Nn    2048
#define Hn    8
#define Dn    64
#define Fn    512
#define ROWS  (Bn * Nn)          // 8192
#define BH    (Bn * Hn)          // 32
#define SLOPE 0.2f

// Scratch (device globals)
__device__ float g_Wh[Bn * Nn * Fn];                    // leaky_relu(h @ W_r)
__device__ float g_er[BH * Nn];
__device__ float g_p [BH * Nn];                         // [b][h][j]
__device__ float g_pT[Bn * Nn * Hn];                    // [b][j][h] head-minor
__device__ float g_S [BH * Nn];
__device__ __nv_bfloat16 g_adjb[(size_t)Bn * Nn * Nn];  // adj as bf16 (exact)
__device__ __nv_bfloat16 g_Bhi[(size_t)Bn * Fn * Nn];   // K-major hi limb of p*Wh
__device__ __nv_bfloat16 g_Blo[(size_t)Bn * Fn * Nn];   // K-major lo limb
__device__ __nv_bfloat16 g_hhi[(size_t)ROWS * Fn];      // h hi limb
__device__ __nv_bfloat16 g_hlo[(size_t)ROWS * Fn];      // h lo limb
__device__ __nv_bfloat16 g_Wthi[Fn * Fn];               // W_r^T hi limb [n][k]
__device__ __nv_bfloat16 g_Wtlo[Fn * Fn];               // W_r^T lo limb

// ---------------------------------------------------------------------------
// Portable PTX helpers (compute_103-safe: no tcgen05)
// ---------------------------------------------------------------------------
__device__ __forceinline__ uint32_t smem_u32(const void* p) {
    uint32_t a;
    asm("{ .reg .u64 t; cvta.to.shared.u64 t, %1; cvt.u32.u64 %0, t; }"
        : "=r"(a) : "l"(p));
    return a;
}
#define SWZ(x) ((x) ^ (((x) >> 3) & 0x70))

#define CP_ASYNC16(dst, src) \
    asm volatile("cp.async.cg.shared.global [%0], [%1], 16;" \
                 :: "r"(dst), "l"(src) : "memory")
#define CP_COMMIT() asm volatile("cp.async.commit_group;" ::: "memory")
#define CP_WAIT(n)  asm volatile("cp.async.wait_group %0;" :: "n"(n) : "memory")

__device__ __forceinline__ void ldsm_x4(uint32_t* r, uint32_t addr) {
    asm volatile("ldmatrix.sync.aligned.m8n8.x4.shared.b16 {%0,%1,%2,%3}, [%4];"
                 : "=r"(r[0]), "=r"(r[1]), "=r"(r[2]), "=r"(r[3]) : "r"(addr));
}

__device__ __forceinline__ void mma16816(float* d, const uint32_t* a,
                                         uint32_t b0, uint32_t b1) {
    asm volatile(
        "mma.sync.aligned.m16n8k16.row.col.f32.bf16.bf16.f32 "
        "{%0,%1,%2,%3}, {%4,%5,%6,%7}, {%8,%9}, {%0,%1,%2,%3};"
        : "+f"(d[0]), "+f"(d[1]), "+f"(d[2]), "+f"(d[3])
        : "r"(a[0]), "r"(a[1]), "r"(a[2]), "r"(a[3]), "r"(b0), "r"(b1));
}

// ---------------------------------------------------------------------------
// Kernel 0a: split h into bf16 hi/lo.  8 elems/thread.
// ---------------------------------------------------------------------------
__global__ void hsplit_kernel(const float* __restrict__ h) {
    const size_t idx = (size_t)(blockIdx.x * blockDim.x + threadIdx.x) * 8;
    float4 x0 = *(const float4*)&h[idx];
    float4 x1 = *(const float4*)&h[idx + 4];
    float xs[8] = {x0.x, x0.y, x0.z, x0.w, x1.x, x1.y, x1.z, x1.w};
    __nv_bfloat16 hi[8], lo[8];
#pragma unroll
    for (int i = 0; i < 8; i++) {
        hi[i] = __float2bfloat16(xs[i]);
        lo[i] = __float2bfloat16(xs[i] - __bfloat162float(hi[i]));
    }
    *(uint4*)&g_hhi[idx] = *(uint4*)hi;
    *(uint4*)&g_hlo[idx] = *(uint4*)lo;
}

// ---------------------------------------------------------------------------
// Kernel 0b: W_r^T split.  64x64 tiles, 256 threads.
// ---------------------------------------------------------------------------
__global__ void wtsplit_kernel(const float* __restrict__ W) {
    __shared__ float ts[64][65];
    const int k0 = blockIdx.x * 64;
    const int n0 = blockIdx.y * 64;
    const int t  = threadIdx.x;
#pragma unroll
    for (int it = 0; it < 16; it++) {
        int idx = it * 256 + t;
        int r = idx >> 6, c = idx & 63;
        ts[r][c] = W[(size_t)(k0 + r) * Fn + n0 + c];
    }
    __syncthreads();
#pragma unroll
    for (int it = 0; it < 16; it++) {
        int idx = it * 256 + t;
        int r = idx >> 6, c = idx & 63;   // r = n index, c = k index
        float x = ts[c][r];
        __nv_bfloat16 hi = __float2bfloat16(x);
        g_Wthi[(size_t)(n0 + r) * Fn + k0 + c] = hi;
        g_Wtlo[(size_t)(n0 + r) * Fn + k0 + c] =
            __float2bfloat16(x - __bfloat162float(hi));
    }
}

// ---------------------------------------------------------------------------
// Kernel 1: Wh = leaky_relu(h @ W_r) via HMMA, bf16 hi/lo 3-product scheme.
// CTA 128x128, K-slab 64, K=512 (8 slabs), 8 warps (2M x 4N), 2-stage cp.async.
// SMEM/stage: Ahi|Alo|Bhi|Blo 16KB each = 64KB; x2 stages = 128KB.
// ---------------------------------------------------------------------------
#define WH_STG   65536
#define WH_SMEM  (2 * WH_STG)
#define WOFF_AH  0
#define WOFF_AL  16384
#define WOFF_BH  32768
#define WOFF_BL  49152

__global__ void __launch_bounds__(256) gemm_wh_mma_kernel() {
    extern __shared__ __align__(1024) char smem[];
    const uint32_t sb = smem_u32(smem);

    const int t   = threadIdx.x;
    const int wid = t >> 5, lane = t & 31;
    const int i0  = blockIdx.x * 128;   // rows of h
    const int n0  = blockIdx.y * 128;   // cols of W

    const __nv_bfloat16* gAh = g_hhi + (size_t)i0 * Fn;
    const __nv_bfloat16* gAl = g_hlo + (size_t)i0 * Fn;
    const __nv_bfloat16* gBh = g_Wthi + (size_t)n0 * Fn;
    const __nv_bfloat16* gBl = g_Wtlo + (size_t)n0 * Fn;

    auto load_stage = [&](int slab, int stg) {
        const int k0 = slab * 64;
        const uint32_t base = sb + stg * WH_STG;
#pragma unroll
        for (int it = 0; it < 4; it++) {
            int c = it * 256 + t;
            int row = c >> 3, chk = c & 7;
            uint32_t doff = SWZ((uint32_t)(row * 128 + chk * 16));
            const size_t goff = (size_t)row * Fn + k0 + chk * 8;
            CP_ASYNC16(base + WOFF_AH + doff, gAh + goff);
            CP_ASYNC16(base + WOFF_AL + doff, gAl + goff);
            CP_ASYNC16(base + WOFF_BH + doff, gBh + goff);
            CP_ASYNC16(base + WOFF_BL + doff, gBl + goff);
        }
    };

    const int wm = wid & 1, wn = wid >> 1;
    const int g  = lane >> 2, tg = lane & 3;
    const int lrow = (lane & 7) + ((lane >> 3) & 1) * 8;
    const int lkb  = (lane >> 4) * 16;

    uint32_t a_off[4], b_off[2];
#pragma unroll
    for (int mt = 0; mt < 4; mt++)
        a_off[mt] = (uint32_t)((wm * 64 + mt * 16 + lrow) * 128 + lkb);
#pragma unroll
    for (int nt2 = 0; nt2 < 2; nt2++)
        b_off[nt2] = (uint32_t)((wn * 32 + nt2 * 16 + lrow) * 128 + lkb);

    float acc[4][4][4];
#pragma unroll
    for (int i = 0; i < 4; i++)
#pragma unroll
        for (int j = 0; j < 4; j++)
#pragma unroll
            for (int k = 0; k < 4; k++) acc[i][j][k] = 0.f;

    load_stage(0, 0);
    CP_COMMIT();

    const int NSLAB = Fn / 64;  // 8
    for (int s = 0; s < NSLAB; s++) {
        const int stg = s & 1;
        if (s + 1 < NSLAB) {
            load_stage(s + 1, stg ^ 1);
            CP_COMMIT();
            CP_WAIT(1);
        } else {
            CP_WAIT(0);
        }
        __syncthreads();

        const uint32_t Ah = sb + stg * WH_STG + WOFF_AH;
        const uint32_t Al = sb + stg * WH_STG + WOFF_AL;
        const uint32_t Bh = sb + stg * WH_STG + WOFF_BH;
        const uint32_t Bl = sb + stg * WH_STG + WOFF_BL;

#pragma unroll
        for (int kk = 0; kk < 4; kk++) {
            uint32_t ahf[4][4], alf[4][4], bhf[2][4], blf[2][4];
#pragma unroll
            for (int mt = 0; mt < 4; mt++) {
                ldsm_x4(ahf[mt], Ah + SWZ(a_off[mt] + kk * 32));
                ldsm_x4(alf[mt], Al + SWZ(a_off[mt] + kk * 32));
            }
#pragma unroll
            for (int nt2 = 0; nt2 < 2; nt2++) {
                ldsm_x4(bhf[nt2], Bh + SWZ(b_off[nt2] + kk * 32));
                ldsm_x4(blf[nt2], Bl + SWZ(b_off[nt2] + kk * 32));
            }
#pragma unroll
            for (int mt = 0; mt < 4; mt++)
#pragma unroll
                for (int nt = 0; nt < 4; nt++) {
                    const int n2 = nt >> 1, hf = nt & 1;
                    mma16816(acc[mt][nt], ahf[mt], bhf[n2][hf], bhf[n2][hf + 2]);
                    mma16816(acc[mt][nt], ahf[mt], blf[n2][hf], blf[n2][hf + 2]);
                    mma16816(acc[mt][nt], alf[mt], bhf[n2][hf], bhf[n2][hf + 2]);
                }
        }
        __syncthreads();
    }

    // Epilogue: leaky_relu, fp32 store
    const int cb = n0 + wn * 32 + tg * 2;
#pragma unroll
    for (int mt = 0; mt < 4; mt++) {
        const int r0 = i0 + wm * 64 + mt * 16 + g;
        const int r1 = r0 + 8;
#pragma unroll
        for (int nt = 0; nt < 4; nt++) {
            const int c = cb + nt * 8;
            float x0 = acc[mt][nt][0], x1 = acc[mt][nt][1];
            float x2 = acc[mt][nt][2], x3 = acc[mt][nt][3];
            float2 v0, v1;
            v0.x = x0 > 0.f ? x0 : SLOPE * x0;
            v0.y = x1 > 0.f ? x1 : SLOPE * x1;
            v1.x = x2 > 0.f ? x2 : SLOPE * x2;
            v1.y = x3 > 0.f ? x3 : SLOPE * x3;
            *(float2*)&g_Wh[(size_t)r0 * Fn + c] = v0;
            *(float2*)&g_Wh[(size_t)r1 * Fn + c] = v1;
        }
    }
}

// ---------------------------------------------------------------------------
// Kernel 2: er[row] = dot(Wh[row, 0:64], a)
// ---------------------------------------------------------------------------
__global__ void er_kernel(const float* __restrict__ a) {
    const int warp = (blockIdx.x * blockDim.x + threadIdx.x) >> 5;
    const int lane = threadIdx.x & 31;
    if (warp >= BH * Nn) return;
    const float* row = g_Wh + (size_t)warp * Dn;
    float s = row[lane] * a[lane] + row[lane + 32] * a[lane + 32];
#pragma unroll
    for (int o = 16; o; o >>= 1) s += __shfl_down_sync(0xffffffffu, s, o);
    if (lane == 0) g_er[warp] = s;
}

// ---------------------------------------------------------------------------
// Kernel 3: p = exp(er - rowmax); also head-minor copy g_pT
// ---------------------------------------------------------------------------
__global__ void maxexp_kernel() {
    __shared__ float sm[8];
    const int bh = blockIdx.x;
    const int b = bh >> 3, h = bh & 7;
    const float* e = g_er + bh * Nn;
    float mx = -1e30f;
    for (int i = threadIdx.x; i < Nn; i += 256) mx = fmaxf(mx, e[i]);
#pragma unroll
    for (int o = 16; o; o >>= 1) mx = fmaxf(mx, __shfl_xor_sync(0xffffffffu, mx, o));
    if ((threadIdx.x & 31) == 0) sm[threadIdx.x >> 5] = mx;
    __syncthreads();
    float mall = sm[0];
#pragma unroll
    for (int i = 1; i < 8; i++) mall = fmaxf(mall, sm[i]);
    for (int i = threadIdx.x; i < Nn; i += 256) {
        float v = expf(e[i] - mall);
        g_p[bh * Nn + i] = v;
        g_pT[((size_t)b * Nn + i) * Hn + h] = v;
    }
}

// ---------------------------------------------------------------------------
// Kernel 4: FUSED adj conversion + S.  One warp per (b,i) row.
// Reads adj once; writes g_adjb; S[b,h,i] = sum_j adj*p via head-minor pT.
// ---------------------------------------------------------------------------
__global__ void adjs_kernel(const int* __restrict__ adj) {
    const int w    = (blockIdx.x * blockDim.x + threadIdx.x) >> 5;
    const int lane = threadIdx.x & 31;
    if (w >= ROWS) return;
    const int b = w >> 11;
    const int i = w & (Nn - 1);
    const int* arow = adj + (size_t)w * Nn;
    __nv_bfloat16* brow = g_adjb + (size_t)w * Nn;
    const float* pT = g_pT + (size_t)b * Nn * Hn;

    float s[Hn] = {};
#pragma unroll 4
    for (int it = 0; it < 16; it++) {
        const int j = (it * 32 + lane) * 4;
        int4 v = *(const int4*)&arow[j];
        float f0 = (float)v.x, f1 = (float)v.y, f2 = (float)v.z, f3 = (float)v.w;
        __nv_bfloat162 c0 = __floats2bfloat162_rn(f0, f1);
        __nv_bfloat162 c1 = __floats2bfloat162_rn(f2, f3);
        uint2 u;
        u.x = *(uint32_t*)&c0;
        u.y = *(uint32_t*)&c1;
        *(uint2*)&brow[j] = u;
        const float fs[4] = {f0, f1, f2, f3};
#pragma unroll
        for (int q = 0; q < 4; q++) {
            float4 p0 = *(const float4*)&pT[(size_t)(j + q) * Hn];
            float4 p1 = *(const float4*)&pT[(size_t)(j + q) * Hn + 4];
            const float fv = fs[q];
            s[0] += fv * p0.x; s[1] += fv * p0.y;
            s[2] += fv * p0.z; s[3] += fv * p0.w;
            s[4] += fv * p1.x; s[5] += fv * p1.y;
            s[6] += fv * p1.z; s[7] += fv * p1.w;
        }
    }
#pragma unroll
    for (int hh = 0; hh < Hn; hh++) {
        float v = s[hh];
#pragma unroll
        for (int o = 16; o; o >>= 1) v += __shfl_down_sync(0xffffffffu, v, o);
        if (lane == 0) g_S[(size_t)b * Hn * Nn + hh * Nn + i] = v;
    }
}

// ---------------------------------------------------------------------------
// Kernel 4b: build K-major bf16 hi/lo B operand: [b][col=h*64+c][j] = p[j]*Wh[j,c]
// ---------------------------------------------------------------------------
__global__ void bprep_kernel() {
    __shared__ float ts[64][65];
    const int j0 = blockIdx.x * 64;
    const int h  = blockIdx.y;
    const int b  = blockIdx.z;
    const int t  = threadIdx.x;

    const float* Wb = g_Wh + (size_t)(b * Hn + h) * Nn * Dn;
    const float* pb = g_p + (b * Hn + h) * Nn;

#pragma unroll
    for (int it = 0; it < 16; it++) {
        int idx = it * 256 + t;
        int r = idx >> 6, c = idx & 63;
        ts[r][c] = Wb[(size_t)(j0 + r) * Dn + c] * pb[j0 + r];
    }
    __syncthreads();

    __nv_bfloat16* bh = g_Bhi + ((size_t)b * Fn + h * Dn) * Nn;
    __nv_bfloat16* bl = g_Blo + ((size_t)b * Fn + h * Dn) * Nn;
#pragma unroll
    for (int it = 0; it < 16; it++) {
        int idx = it * 256 + t;
        int c = idx >> 6, r = idx & 63;
        float x = ts[r][c];
        __nv_bfloat16 hi = __float2bfloat16(x);
        float lo = x - __bfloat162float(hi);
        bh[(size_t)c * Nn + j0 + r] = hi;
        bl[(size_t)c * Nn + j0 + r] = __float2bfloat16(lo);
    }
}

// ---------------------------------------------------------------------------
// Kernel 5: warp-MMA attention GEMM (unchanged from round 3).
// ---------------------------------------------------------------------------
#define STG_BYTES 49152
#define ATT_SMEM  (2 * STG_BYTES)
#define OFF_A  0
#define OFF_BH 16384
#define OFF_BL 32768

__global__ void __launch_bounds__(256) att_mma_kernel(float* __restrict__ out) {
    extern __shared__ __align__(1024) char smem[];
    const uint32_t sb = smem_u32(smem);

    const int t    = threadIdx.x;
    const int wid  = t >> 5, lane = t & 31;
    const int i0   = blockIdx.x * 128;
    const int n0c  = blockIdx.y * 128;
    const int b    = blockIdx.z;

    const __nv_bfloat16* gA  = g_adjb + ((size_t)b * Nn + i0) * Nn;
    const __nv_bfloat16* gBh = g_Bhi + ((size_t)b * Fn + n0c) * Nn;
    const __nv_bfloat16* gBl = g_Blo + ((size_t)b * Fn + n0c) * Nn;

    auto load_stage = [&](int slab, int stg) {
        const int k0 = slab * 64;
        const uint32_t base = sb + stg * STG_BYTES;
#pragma unroll
        for (int it = 0; it < 4; it++) {
            int c = it * 256 + t;
            int row = c >> 3, chk = c & 7;
            uint32_t doff = SWZ((uint32_t)(row * 128 + chk * 16));
            CP_ASYNC16(base + OFF_A + doff, gA + (size_t)row * Nn + k0 + chk * 8);
            CP_ASYNC16(base + OFF_BH + doff, gBh + (size_t)row * Nn + k0 + chk * 8);
            CP_ASYNC16(base + OFF_BL + doff, gBl + (size_t)row * Nn + k0 + chk * 8);
        }
    };

    const int wm = wid & 1, wn = wid >> 1;
    const int g  = lane >> 2, tg = lane & 3;
    const int lrow = (lane & 7) + ((lane >> 3) & 1) * 8;
    const int lkb  = (lane >> 4) * 16;

    uint32_t a_off[4], b_off[2];
#pragma unroll
    for (int mt = 0; mt < 4; mt++)
        a_off[mt] = (uint32_t)((wm * 64 + mt * 16 + lrow) * 128 + lkb);
#pragma unroll
    for (int nt2 = 0; nt2 < 2; nt2++)
        b_off[nt2] = (uint32_t)((wn * 32 + nt2 * 16 + lrow) * 128 + lkb);

    float acc[4][4][4];
#pragma unroll
    for (int i = 0; i < 4; i++)
#pragma unroll
        for (int j = 0; j < 4; j++)
#pragma unroll
            for (int k = 0; k < 4; k++) acc[i][j][k] = 0.f;

    load_stage(0, 0);
    CP_COMMIT();

    const int NSLAB = Nn / 64;  // 32
    for (int s = 0; s < NSLAB; s++) {
        const int stg = s & 1;
        if (s + 1 < NSLAB) {
            load_stage(s + 1, stg ^ 1);
            CP_COMMIT();
            CP_WAIT(1);
        } else {
            CP_WAIT(0);
        }
        __syncthreads();

        const uint32_t Ab = sb + stg * STG_BYTES + OFF_A;
        const uint32_t Bh = sb + stg * STG_BYTES + OFF_BH;
        const uint32_t Bl = sb + stg * STG_BYTES + OFF_BL;

#pragma unroll
        for (int kk = 0; kk < 4; kk++) {
            uint32_t af[4][4], bhf[2][4], blf[2][4];
#pragma unroll
            for (int mt = 0; mt < 4; mt++)
                ldsm_x4(af[mt], Ab + SWZ(a_off[mt] + kk * 32));
#pragma unroll
            for (int nt2 = 0; nt2 < 2; nt2++) {
                ldsm_x4(bhf[nt2], Bh + SWZ(b_off[nt2] + kk * 32));
                ldsm_x4(blf[nt2], Bl + SWZ(b_off[nt2] + kk * 32));
            }
#pragma unroll
            for (int mt = 0; mt < 4; mt++)
#pragma unroll
                for (int nt = 0; nt < 4; nt++) {
                    const int n2 = nt >> 1, hf = nt & 1;
                    mma16816(acc[mt][nt], af[mt], bhf[n2][hf], bhf[n2][hf + 2]);
                    mma16816(acc[mt][nt], af[mt], blf[n2][hf], blf[n2][hf + 2]);
                }
        }
        __syncthreads();
    }

    const int hwarp = (n0c + wn * 32) >> 6;
    const int cbase = ((wn * 32) & 63) + tg * 2;
    const float* Sb = g_S + (size_t)(b * Hn + hwarp) * Nn;
    float* ob = out + (size_t)(b * Hn + hwarp) * Nn * Dn;

#pragma unroll
    for (int mt = 0; mt < 4; mt++) {
        const int r0 = i0 + wm * 64 + mt * 16 + g;
        const int r1 = r0 + 8;
        float s0 = Sb[r0]; if (s0 == 0.f) s0 = 1.f;
        float s1 = Sb[r1]; if (s1 == 0.f) s1 = 1.f;
        const float inv0 = 1.f / s0, inv1 = 1.f / s1;
#pragma unroll
        for (int nt = 0; nt < 4; nt++) {
            const int c = cbase + nt * 8;
            float x0 = acc[mt][nt][0] * inv0;
            float x1 = acc[mt][nt][1] * inv0;
            float x2 = acc[mt][nt][2] * inv1;
            float x3 = acc[mt][nt][3] * inv1;
            float2 v0, v1;
            v0.x = x0 > 0.f ? x0 : expm1f(x0);
            v0.y = x1 > 0.f ? x1 : expm1f(x1);
            v1.x = x2 > 0.f ? x2 : expm1f(x2);
            v1.y = x3 > 0.f ? x3 : expm1f(x3);
            *(float2*)&ob[(size_t)r0 * Dn + c] = v0;
            *(float2*)&ob[(size_t)r1 * Dn + c] = v1;
        }
    }
}

// ---------------------------------------------------------------------------
// Launch.  Inputs: 0=h f32, 1=adj i32, 2=W_l (unused), 3=W_r f32, 4=a f32
// ---------------------------------------------------------------------------
extern "C" void kernel_launch(void* const* d_in, const int* in_sizes, int n_in,
                              void* d_out, int out_size) {
    const float* h   = (const float*)d_in[0];
    const int*   adj = (const int*)  d_in[1];
    const float* W_r = (const float*)d_in[3];
    const float* a   = (const float*)d_in[4];
    float* out = (float*)d_out;

    static int smem_set = 0;
    if (!smem_set) {
        cudaFuncSetAttribute(att_mma_kernel,
                             cudaFuncAttributeMaxDynamicSharedMemorySize, ATT_SMEM);
        cudaFuncSetAttribute(gemm_wh_mma_kernel,
                             cudaFuncAttributeMaxDynamicSharedMemorySize, WH_SMEM);
        smem_set = 1;
    }

    // 0. operand splits
    hsplit_kernel<<<(ROWS * Fn / 8) / 256, 256>>>(h);
    {
        dim3 grid(Fn / 64, Fn / 64);
        wtsplit_kernel<<<grid, 256>>>(W_r);
    }
    // 1. Wh = leaky_relu(h @ W_r)  — HMMA hi/lo
    {
        dim3 grid(ROWS / 128, Fn / 128);
        gemm_wh_mma_kernel<<<grid, 256, WH_SMEM>>>();
    }
    // 2. er = Wh_rows . a
    {
        const int warps = BH * Nn;
        er_kernel<<<(warps * 32 + 255) / 256, 256>>>(a);
    }
    // 3. p = exp(er - max)  (+ head-minor copy)
    maxexp_kernel<<<BH, 256>>>();
    // 4. fused adj->bf16 + S
    adjs_kernel<<<ROWS * 32 / 256, 256>>>(adj);
    // 4b. B operand hi/lo
    {
        dim3 grid(Nn / 64, Hn, Bn);
        bprep_kernel<<<grid, 256>>>();
    }
    // 5. out = elu(D^-1 Adj @ (p .* Wh))  — HMMA
    {
        dim3 grid(Nn / 128, Fn / 128, Bn);
        att_mma_kernel<<<grid, 256, ATT_SMEM>>>(out);
    }
}

// round 6
// speedup vs baseline: 1.0450x; 1.0450x over previous
#include <cuda_runtime.h>
#include <cuda_bf16.h>
#include <math.h>
#include <stdint.h>

// Problem constants
#define Bn    4
#define Nn    2048
#define Hn    8
#define Dn    64
#define Fn    512
#define ROWS  (Bn * Nn)          // 8192
#define BH    (Bn * Hn)          // 32
#define SLOPE 0.2f

// Scratch (device globals)
__device__ float g_Wh[Bn * Nn * Fn];                    // leaky_relu(h @ W_r)
__device__ float g_er[BH * Nn];                         // flat [65536]: row R*8+cg
__device__ float g_p [BH * Nn];                         // [b][h][j]
__device__ float g_pT[Bn * Nn * Hn];                    // [b][j][h] head-minor
__device__ float g_S [BH * Nn];
__device__ __nv_bfloat16 g_adjb[(size_t)Bn * Nn * Nn];  // adj as bf16 (exact)
__device__ __nv_bfloat16 g_Bhi[(size_t)Bn * Fn * Nn];   // K-major hi limb of p*Wh
__device__ __nv_bfloat16 g_Blo[(size_t)Bn * Fn * Nn];   // K-major lo limb
__device__ __nv_bfloat16 g_hhi[(size_t)ROWS * Fn];      // h hi limb
__device__ __nv_bfloat16 g_hlo[(size_t)ROWS * Fn];      // h lo limb
__device__ __nv_bfloat16 g_Wthi[Fn * Fn];               // W_r^T hi limb [n][k]
__device__ __nv_bfloat16 g_Wtlo[Fn * Fn];               // W_r^T lo limb

// ---------------------------------------------------------------------------
// Portable PTX helpers (compute_103-safe)
// ---------------------------------------------------------------------------
__device__ __forceinline__ uint32_t smem_u32(const void* p) {
    uint32_t a;
    asm("{ .reg .u64 t; cvta.to.shared.u64 t, %1; cvt.u32.u64 %0, t; }"
        : "=r"(a) : "l"(p));
    return a;
}
#define SWZ(x) ((x) ^ (((x) >> 3) & 0x70))

#define CP_ASYNC16(dst, src) \
    asm volatile("cp.async.cg.shared.global [%0], [%1], 16;" \
                 :: "r"(dst), "l"(src) : "memory")
#define CP_COMMIT() asm volatile("cp.async.commit_group;" ::: "memory")
#define CP_WAIT(n)  asm volatile("cp.async.wait_group %0;" :: "n"(n) : "memory")

__device__ __forceinline__ void ldsm_x4(uint32_t* r, uint32_t addr) {
    asm volatile("ldmatrix.sync.aligned.m8n8.x4.shared.b16 {%0,%1,%2,%3}, [%4];"
                 : "=r"(r[0]), "=r"(r[1]), "=r"(r[2]), "=r"(r[3]) : "r"(addr));
}

__device__ __forceinline__ void mma16816(float* d, const uint32_t* a,
                                         uint32_t b0, uint32_t b1) {
    asm volatile(
        "mma.sync.aligned.m16n8k16.row.col.f32.bf16.bf16.f32 "
        "{%0,%1,%2,%3}, {%4,%5,%6,%7}, {%8,%9}, {%0,%1,%2,%3};"
        : "+f"(d[0]), "+f"(d[1]), "+f"(d[2]), "+f"(d[3])
        : "r"(a[0]), "r"(a[1]), "r"(a[2]), "r"(a[3]), "r"(b0), "r"(b1));
}

// ---------------------------------------------------------------------------
// Kernel 0a: split h into bf16 hi/lo.  8 elems/thread.
// ---------------------------------------------------------------------------
__global__ void hsplit_kernel(const float* __restrict__ h) {
    const size_t idx = (size_t)(blockIdx.x * blockDim.x + threadIdx.x) * 8;
    float4 x0 = *(const float4*)&h[idx];
    float4 x1 = *(const float4*)&h[idx + 4];
    float xs[8] = {x0.x, x0.y, x0.z, x0.w, x1.x, x1.y, x1.z, x1.w};
    __nv_bfloat16 hi[8], lo[8];
#pragma unroll
    for (int i = 0; i < 8; i++) {
        hi[i] = __float2bfloat16(xs[i]);
        lo[i] = __float2bfloat16(xs[i] - __bfloat162float(hi[i]));
    }
    *(uint4*)&g_hhi[idx] = *(uint4*)hi;
    *(uint4*)&g_hlo[idx] = *(uint4*)lo;
}

// ---------------------------------------------------------------------------
// Kernel 0b: W_r^T split.  64x64 tiles, 256 threads.
// ---------------------------------------------------------------------------
__global__ void wtsplit_kernel(const float* __restrict__ W) {
    __shared__ float ts[64][65];
    const int k0 = blockIdx.x * 64;
    const int n0 = blockIdx.y * 64;
    const int t  = threadIdx.x;
#pragma unroll
    for (int it = 0; it < 16; it++) {
        int idx = it * 256 + t;
        int r = idx >> 6, c = idx & 63;
        ts[r][c] = W[(size_t)(k0 + r) * Fn + n0 + c];
    }
    __syncthreads();
#pragma unroll
    for (int it = 0; it < 16; it++) {
        int idx = it * 256 + t;
        int r = idx >> 6, c = idx & 63;
        float x = ts[c][r];
        __nv_bfloat16 hi = __float2bfloat16(x);
        g_Wthi[(size_t)(n0 + r) * Fn + k0 + c] = hi;
        g_Wtlo[(size_t)(n0 + r) * Fn + k0 + c] =
            __float2bfloat16(x - __bfloat162float(hi));
    }
}

// ---------------------------------------------------------------------------
// Kernel 1: Wh = leaky_relu(h @ W_r) via HMMA hi/lo (3 products).
// CTA 128x256, 512 threads (16 warps = 2M x 8N), BK=64, 2-stage cp.async.
// Fused er: for source row R and 64-col group cg, flat er row = R*8 + cg
// (raw reshape semantics!), er = dot(group cols, a[col&63]).
// SMEM/stage: Ahi 16K | Alo 16K | Bhi 32K | Blo 32K = 96KB; x2 = 192KB.
// ---------------------------------------------------------------------------
#define WH_STG   98304
#define WH_SMEM  (2 * WH_STG)
#define WOFF_AH  0
#define WOFF_AL  16384
#define WOFF_BH  32768
#define WOFF_BL  65536

__global__ void __launch_bounds__(512) gemm_wh_mma_kernel(const float* __restrict__ avec) {
    extern __shared__ __align__(1024) char smem[];
    const uint32_t sb = smem_u32(smem);

    const int t   = threadIdx.x;
    const int wid = t >> 5, lane = t & 31;
    const int i0  = blockIdx.x * 128;   // source rows
    const int n0  = blockIdx.y * 256;   // source cols

    const __nv_bfloat16* gAh = g_hhi + (size_t)i0 * Fn;
    const __nv_bfloat16* gAl = g_hlo + (size_t)i0 * Fn;
    const __nv_bfloat16* gBh = g_Wthi + (size_t)n0 * Fn;
    const __nv_bfloat16* gBl = g_Wtlo + (size_t)n0 * Fn;

    auto load_stage = [&](int slab, int stg) {
        const int k0 = slab * 64;
        const uint32_t base = sb + stg * WH_STG;
#pragma unroll
        for (int it = 0; it < 2; it++) {          // A: 128 rows x 8 chunks
            int c = it * 512 + t;
            int row = c >> 3, chk = c & 7;
            uint32_t doff = SWZ((uint32_t)(row * 128 + chk * 16));
            const size_t goff = (size_t)row * Fn + k0 + chk * 8;
            CP_ASYNC16(base + WOFF_AH + doff, gAh + goff);
            CP_ASYNC16(base + WOFF_AL + doff, gAl + goff);
        }
#pragma unroll
        for (int it = 0; it < 4; it++) {          // B: 256 rows x 8 chunks
            int c = it * 512 + t;
            int row = c >> 3, chk = c & 7;
            uint32_t doff = SWZ((uint32_t)(row * 128 + chk * 16));
            const size_t goff = (size_t)row * Fn + k0 + chk * 8;
            CP_ASYNC16(base + WOFF_BH + doff, gBh + goff);
            CP_ASYNC16(base + WOFF_BL + doff, gBl + goff);
        }
    };

    const int wm = wid & 1, wn = wid >> 1;        // wm<2 (64 rows), wn<8 (32 cols)
    const int g  = lane >> 2, tg = lane & 3;
    const int lrow = (lane & 7) + ((lane >> 3) & 1) * 8;
    const int lkb  = (lane >> 4) * 16;

    uint32_t a_off[4], b_off[2];
#pragma unroll
    for (int mt = 0; mt < 4; mt++)
        a_off[mt] = (uint32_t)((wm * 64 + mt * 16 + lrow) * 128 + lkb);
#pragma unroll
    for (int nt2 = 0; nt2 < 2; nt2++)
        b_off[nt2] = (uint32_t)((wn * 32 + nt2 * 16 + lrow) * 128 + lkb);

    float acc[4][4][4];
#pragma unroll
    for (int i = 0; i < 4; i++)
#pragma unroll
        for (int j = 0; j < 4; j++)
#pragma unroll
            for (int k = 0; k < 4; k++) acc[i][j][k] = 0.f;

    load_stage(0, 0);
    CP_COMMIT();

    const int NSLAB = Fn / 64;  // 8
    for (int s = 0; s < NSLAB; s++) {
        const int stg = s & 1;
        if (s + 1 < NSLAB) {
            load_stage(s + 1, stg ^ 1);
            CP_COMMIT();
            CP_WAIT(1);
        } else {
            CP_WAIT(0);
        }
        __syncthreads();

        const uint32_t Ah = sb + stg * WH_STG + WOFF_AH;
        const uint32_t Al = sb + stg * WH_STG + WOFF_AL;
        const uint32_t Bh = sb + stg * WH_STG + WOFF_BH;
        const uint32_t Bl = sb + stg * WH_STG + WOFF_BL;

#pragma unroll
        for (int kk = 0; kk < 4; kk++) {
            uint32_t bhf[2][4], blf[2][4], af[4][4];
#pragma unroll
            for (int nt2 = 0; nt2 < 2; nt2++) {
                ldsm_x4(bhf[nt2], Bh + SWZ(b_off[nt2] + kk * 32));
                ldsm_x4(blf[nt2], Bl + SWZ(b_off[nt2] + kk * 32));
            }
#pragma unroll
            for (int mt = 0; mt < 4; mt++)
                ldsm_x4(af[mt], Ah + SWZ(a_off[mt] + kk * 32));
#pragma unroll
            for (int mt = 0; mt < 4; mt++)
#pragma unroll
                for (int nt = 0; nt < 4; nt++) {
                    const int n2 = nt >> 1, hf = nt & 1;
                    mma16816(acc[mt][nt], af[mt], bhf[n2][hf], bhf[n2][hf + 2]);
                    mma16816(acc[mt][nt], af[mt], blf[n2][hf], blf[n2][hf + 2]);
                }
            // A-lo product (x Bhi only) — reuse af registers
#pragma unroll
            for (int mt = 0; mt < 4; mt++)
                ldsm_x4(af[mt], Al + SWZ(a_off[mt] + kk * 32));
#pragma unroll
            for (int mt = 0; mt < 4; mt++)
#pragma unroll
                for (int nt = 0; nt < 4; nt++) {
                    const int n2 = nt >> 1, hf = nt & 1;
                    mma16816(acc[mt][nt], af[mt], bhf[n2][hf], bhf[n2][hf + 2]);
                }
        }
        __syncthreads();
    }

    // Epilogue: leaky_relu + store + fused er partials
    float a_c0[4], a_c1[4];
#pragma unroll
    for (int nt = 0; nt < 4; nt++) {
        const int c63 = (wn * 32 + tg * 2 + nt * 8) & 63;
        a_c0[nt] = avec[c63];
        a_c1[nt] = avec[c63 + 1];
    }

    float erp[4][2];
    const int cb = n0 + wn * 32 + tg * 2;
#pragma unroll
    for (int mt = 0; mt < 4; mt++) {
        const int r0 = i0 + wm * 64 + mt * 16 + g;
        const int r1 = r0 + 8;
        float e0 = 0.f, e1 = 0.f;
#pragma unroll
        for (int nt = 0; nt < 4; nt++) {
            const int c = cb + nt * 8;
            float x0 = acc[mt][nt][0], x1 = acc[mt][nt][1];
            float x2 = acc[mt][nt][2], x3 = acc[mt][nt][3];
            float2 v0, v1;
            v0.x = x0 > 0.f ? x0 : SLOPE * x0;
            v0.y = x1 > 0.f ? x1 : SLOPE * x1;
            v1.x = x2 > 0.f ? x2 : SLOPE * x2;
            v1.y = x3 > 0.f ? x3 : SLOPE * x3;
            *(float2*)&g_Wh[(size_t)r0 * Fn + c] = v0;
            *(float2*)&g_Wh[(size_t)r1 * Fn + c] = v1;
            e0 += v0.x * a_c0[nt] + v0.y * a_c1[nt];
            e1 += v1.x * a_c0[nt] + v1.y * a_c1[nt];
        }
        erp[mt][0] = e0;
        erp[mt][1] = e1;
    }

    // Reduce er over tg lanes, stash per-warp 32-col band sums in smem.
    float* er_sm = (float*)smem;    // [8 bands][128 rows] = 4KB (stages dead now)
    __syncthreads();
#pragma unroll
    for (int mt = 0; mt < 4; mt++) {
#pragma unroll
        for (int rr = 0; rr < 2; rr++) {
            float v = erp[mt][rr];
            v += __shfl_xor_sync(0xffffffffu, v, 1);
            v += __shfl_xor_sync(0xffffffffu, v, 2);
            if (tg == 0)
                er_sm[wn * 128 + wm * 64 + mt * 16 + g + rr * 8] = v;
        }
    }
    __syncthreads();
    // Combine the two 32-col bands of each 64-col group; write flat er.
    // RAW RESHAPE: flat er row for (source row R, col group cg) = R*8 + cg.
    {
        const int k = t >> 7, r = t & 127;      // k<4 col groups in this CTA
        const int cg = blockIdx.y * 4 + k;      // global 64-col group (0..7)
        const int row = i0 + r;                 // global source row
        g_er[(size_t)row * 8 + cg] =
            er_sm[(2 * k) * 128 + r] + er_sm[(2 * k + 1) * 128 + r];
    }
}

// ---------------------------------------------------------------------------
// Kernel 3: p = exp(er - rowmax); also head-minor copy g_pT
// ---------------------------------------------------------------------------
__global__ void maxexp_kernel() {
    __shared__ float sm[8];
    const int bh = blockIdx.x;
    const int b = bh >> 3, h = bh & 7;
    const float* e = g_er + bh * Nn;
    float mx = -1e30f;
    for (int i = threadIdx.x; i < Nn; i += 256) mx = fmaxf(mx, e[i]);
#pragma unroll
    for (int o = 16; o; o >>= 1) mx = fmaxf(mx, __shfl_xor_sync(0xffffffffu, mx, o));
    if ((threadIdx.x & 31) == 0) sm[threadIdx.x >> 5] = mx;
    __syncthreads();
    float mall = sm[0];
#pragma unroll
    for (int i = 1; i < 8; i++) mall = fmaxf(mall, sm[i]);
    for (int i = threadIdx.x; i < Nn; i += 256) {
        float v = expf(e[i] - mall);
        g_p[bh * Nn + i] = v;
        g_pT[((size_t)b * Nn + i) * Hn + h] = v;
    }
}

// ---------------------------------------------------------------------------
// Kernel 4: FUSED adj conversion + S.  One warp per (b,i) row.
// ---------------------------------------------------------------------------
__global__ void adjs_kernel(const int* __restrict__ adj) {
    const int w    = (blockIdx.x * blockDim.x + threadIdx.x) >> 5;
    const int lane = threadIdx.x & 31;
    if (w >= ROWS) return;
    const int b = w >> 11;
    const int i = w & (Nn - 1);
    const int* arow = adj + (size_t)w * Nn;
    __nv_bfloat16* brow = g_adjb + (size_t)w * Nn;
    const float* pT = g_pT + (size_t)b * Nn * Hn;

    float s[Hn] = {};
#pragma unroll 4
    for (int it = 0; it < 16; it++) {
        const int j = (it * 32 + lane) * 4;
        int4 v = *(const int4*)&arow[j];
        float f0 = (float)v.x, f1 = (float)v.y, f2 = (float)v.z, f3 = (float)v.w;
        __nv_bfloat162 c0 = __floats2bfloat162_rn(f0, f1);
        __nv_bfloat162 c1 = __floats2bfloat162_rn(f2, f3);
        uint2 u;
        u.x = *(uint32_t*)&c0;
        u.y = *(uint32_t*)&c1;
        *(uint2*)&brow[j] = u;
        const float fs[4] = {f0, f1, f2, f3};
#pragma unroll
        for (int q = 0; q < 4; q++) {
            float4 p0 = *(const float4*)&pT[(size_t)(j + q) * Hn];
            float4 p1 = *(const float4*)&pT[(size_t)(j + q) * Hn + 4];
            const float fv = fs[q];
            s[0] += fv * p0.x; s[1] += fv * p0.y;
            s[2] += fv * p0.z; s[3] += fv * p0.w;
            s[4] += fv * p1.x; s[5] += fv * p1.y;
            s[6] += fv * p1.z; s[7] += fv * p1.w;
        }
    }
#pragma unroll
    for (int hh = 0; hh < Hn; hh++) {
        float v = s[hh];
#pragma unroll
        for (int o = 16; o; o >>= 1) v += __shfl_down_sync(0xffffffffu, v, o);
        if (lane == 0) g_S[(size_t)b * Hn * Nn + hh * Nn + i] = v;
    }
}

// ---------------------------------------------------------------------------
// Kernel 4b: K-major bf16 hi/lo B operand: [b][col=h*64+c][j] = p[j]*Wh[j,c]
// (g_Wh interpreted flat as [B,H,N,d] — correct raw-reshape view.)
// ---------------------------------------------------------------------------
__global__ void bprep_kernel() {
    __shared__ float ts[64][65];
    const int j0 = blockIdx.x * 64;
    const int h  = blockIdx.y;
    const int b  = blockIdx.z;
    const int t  = threadIdx.x;

    const float* Wb = g_Wh + (size_t)(b * Hn + h) * Nn * Dn;
    const float* pb = g_p + (b * Hn + h) * Nn;

#pragma unroll
    for (int it = 0; it < 16; it++) {
        int idx = it * 256 + t;
        int r = idx >> 6, c = idx & 63;
        ts[r][c] = Wb[(size_t)(j0 + r) * Dn + c] * pb[j0 + r];
    }
    __syncthreads();

    __nv_bfloat16* bh = g_Bhi + ((size_t)b * Fn + h * Dn) * Nn;
    __nv_bfloat16* bl = g_Blo + ((size_t)b * Fn + h * Dn) * Nn;
#pragma unroll
    for (int it = 0; it < 16; it++) {
        int idx = it * 256 + t;
        int c = idx >> 6, r = idx & 63;
        float x = ts[r][c];
        __nv_bfloat16 hi = __float2bfloat16(x);
        float lo = x - __bfloat162float(hi);
        bh[(size_t)c * Nn + j0 + r] = hi;
        bl[(size_t)c * Nn + j0 + r] = __float2bfloat16(lo);
    }
}

// ---------------------------------------------------------------------------
// Kernel 5: warp-MMA attention GEMM.
// CTA 128x256, 512 threads (16 warps = 2M x 8N), BK=64, 2-stage.
// SMEM/stage: A 16K | Bhi 32K | Blo 32K = 80KB; x2 = 160KB.
// ---------------------------------------------------------------------------
#define STG_BYTES 81920
#define ATT_SMEM  (2 * STG_BYTES)
#define OFF_A  0
#define OFF_BH 16384
#define OFF_BL 49152

__global__ void __launch_bounds__(512) att_mma_kernel(float* __restrict__ out) {
    extern __shared__ __align__(1024) char smem[];
    const uint32_t sb = smem_u32(smem);

    const int t    = threadIdx.x;
    const int wid  = t >> 5, lane = t & 31;
    const int i0   = blockIdx.x * 128;
    const int n0c  = blockIdx.y * 256;
    const int b    = blockIdx.z;

    const __nv_bfloat16* gA  = g_adjb + ((size_t)b * Nn + i0) * Nn;
    const __nv_bfloat16* gBh = g_Bhi + ((size_t)b * Fn + n0c) * Nn;
    const __nv_bfloat16* gBl = g_Blo + ((size_t)b * Fn + n0c) * Nn;

    auto load_stage = [&](int slab, int stg) {
        const int k0 = slab * 64;
        const uint32_t base = sb + stg * STG_BYTES;
#pragma unroll
        for (int it = 0; it < 2; it++) {          // A: 128 rows
            int c = it * 512 + t;
            int row = c >> 3, chk = c & 7;
            uint32_t doff = SWZ((uint32_t)(row * 128 + chk * 16));
            CP_ASYNC16(base + OFF_A + doff, gA + (size_t)row * Nn + k0 + chk * 8);
        }
#pragma unroll
        for (int it = 0; it < 4; it++) {          // B: 256 rows
            int c = it * 512 + t;
            int row = c >> 3, chk = c & 7;
            uint32_t doff = SWZ((uint32_t)(row * 128 + chk * 16));
            CP_ASYNC16(base + OFF_BH + doff, gBh + (size_t)row * Nn + k0 + chk * 8);
            CP_ASYNC16(base + OFF_BL + doff, gBl + (size_t)row * Nn + k0 + chk * 8);
        }
    };

    const int wm = wid & 1, wn = wid >> 1;        // wm<2, wn<8
    const int g  = lane >> 2, tg = lane & 3;
    const int lrow = (lane & 7) + ((lane >> 3) & 1) * 8;
    const int lkb  = (lane >> 4) * 16;

    uint32_t a_off[4], b_off[2];
#pragma unroll
    for (int mt = 0; mt < 4; mt++)
        a_off[mt] = (uint32_t)((wm * 64 + mt * 16 + lrow) * 128 + lkb);
#pragma unroll
    for (int nt2 = 0; nt2 < 2; nt2++)
        b_off[nt2] = (uint32_t)((wn * 32 + nt2 * 16 + lrow) * 128 + lkb);

    float acc[4][4][4];
#pragma unroll
    for (int i = 0; i < 4; i++)
#pragma unroll
        for (int j = 0; j < 4; j++)
#pragma unroll
            for (int k = 0; k < 4; k++) acc[i][j][k] = 0.f;

    load_stage(0, 0);
    CP_COMMIT();

    const int NSLAB = Nn / 64;  // 32
    for (int s = 0; s < NSLAB; s++) {
        const int stg = s & 1;
        if (s + 1 < NSLAB) {
            load_stage(s + 1, stg ^ 1);
            CP_COMMIT();
            CP_WAIT(1);
        } else {
            CP_WAIT(0);
        }
        __syncthreads();

        const uint32_t Ab = sb + stg * STG_BYTES + OFF_A;
        const uint32_t Bh = sb + stg * STG_BYTES + OFF_BH;
        const uint32_t Bl = sb + stg * STG_BYTES + OFF_BL;

#pragma unroll
        for (int kk = 0; kk < 4; kk++) {
            uint32_t af[4][4], bhf[2][4], blf[2][4];
#pragma unroll
            for (int mt = 0; mt < 4; mt++)
                ldsm_x4(af[mt], Ab + SWZ(a_off[mt] + kk * 32));
#pragma unroll
            for (int nt2 = 0; nt2 < 2; nt2++) {
                ldsm_x4(bhf[nt2], Bh + SWZ(b_off[nt2] + kk * 32));
                ldsm_x4(blf[nt2], Bl + SWZ(b_off[nt2] + kk * 32));
            }
#pragma unroll
            for (int mt = 0; mt < 4; mt++)
#pragma unroll
                for (int nt = 0; nt < 4; nt++) {
                    const int n2 = nt >> 1, hf = nt & 1;
                    mma16816(acc[mt][nt], af[mt], bhf[n2][hf], bhf[n2][hf + 2]);
                    mma16816(acc[mt][nt], af[mt], blf[n2][hf], blf[n2][hf + 2]);
                }
        }
        __syncthreads();
    }

    const int hwarp = (n0c + wn * 32) >> 6;
    const int cbase = ((wn * 32) & 63) + tg * 2;
    const float* Sb = g_S + (size_t)(b * Hn + hwarp) * Nn;
    float* ob = out + (size_t)(b * Hn + hwarp) * Nn * Dn;

#pragma unroll
    for (int mt = 0; mt < 4; mt++) {
        const int r0 = i0 + wm * 64 + mt * 16 + g;
        const int r1 = r0 + 8;
        float s0 = Sb[r0]; if (s0 == 0.f) s0 = 1.f;
        float s1 = Sb[r1]; if (s1 == 0.f) s1 = 1.f;
        const float inv0 = 1.f / s0, inv1 = 1.f / s1;
#pragma unroll
        for (int nt = 0; nt < 4; nt++) {
            const int c = cbase + nt * 8;
            float x0 = acc[mt][nt][0] * inv0;
            float x1 = acc[mt][nt][1] * inv0;
            float x2 = acc[mt][nt][2] * inv1;
            float x3 = acc[mt][nt][3] * inv1;
            float2 v0, v1;
            v0.x = x0 > 0.f ? x0 : expm1f(x0);
            v0.y = x1 > 0.f ? x1 : expm1f(x1);
            v1.x = x2 > 0.f ? x2 : expm1f(x2);
            v1.y = x3 > 0.f ? x3 : expm1f(x3);
            *(float2*)&ob[(size_t)r0 * Dn + c] = v0;
            *(float2*)&ob[(size_t)r1 * Dn + c] = v1;
        }
    }
}

// ---------------------------------------------------------------------------
// Launch.  Inputs: 0=h f32, 1=adj i32, 2=W_l (unused), 3=W_r f32, 4=a f32
// ---------------------------------------------------------------------------
extern "C" void kernel_launch(void* const* d_in, const int* in_sizes, int n_in,
                              void* d_out, int out_size) {
    const float* h   = (const float*)d_in[0];
    const int*   adj = (const int*)  d_in[1];
    const float* W_r = (const float*)d_in[3];
    const float* a   = (const float*)d_in[4];
    float* out = (float*)d_out;

    cudaFuncSetAttribute(att_mma_kernel,
                         cudaFuncAttributeMaxDynamicSharedMemorySize, ATT_SMEM);
    cudaFuncSetAttribute(gemm_wh_mma_kernel,
                         cudaFuncAttributeMaxDynamicSharedMemorySize, WH_SMEM);

    // 0. operand splits
    hsplit_kernel<<<(ROWS * Fn / 8) / 256, 256>>>(h);
    {
        dim3 grid(Fn / 64, Fn / 64);
        wtsplit_kernel<<<grid, 256>>>(W_r);
    }
    // 1. Wh = leaky_relu(h @ W_r) + fused er   — HMMA hi/lo, 16 warps
    {
        dim3 grid(ROWS / 128, Fn / 256);
        gemm_wh_mma_kernel<<<grid, 512, WH_SMEM>>>(a);
    }
    // 3. p = exp(er - max)  (+ head-minor copy)
    maxexp_kernel<<<BH, 256>>>();
    // 4. fused adj->bf16 + S
    adjs_kernel<<<ROWS * 32 / 256, 256>>>(adj);
    // 4b. B operand hi/lo
    {
        dim3 grid(Nn / 64, Hn, Bn);
        bprep_kernel<<<grid, 256>>>();
    }
    // 5. out = elu(D^-1 Adj @ (p .* Wh))  — HMMA, 16 warps
    {
        dim3 grid(Nn / 128, Fn / 256, Bn);
        att_mma_kernel<<<grid, 512, ATT_SMEM>>>(out);
    }
}

// round 7
// speedup vs baseline: 1.4574x; 1.3946x over previous
#include <cuda_runtime.h>
#include <cuda_bf16.h>
#include <math.h>
#include <stdint.h>

// Problem constants
#define Bn    4
#define Nn    2048
#define Hn    8
#define Dn    64
#define Fn    512
#define ROWS  (Bn * Nn)          // 8192
#define BH    (Bn * Hn)          // 32
#define SLOPE 0.2f

// Scratch (device globals)
__device__ float g_Wh[Bn * Nn * Fn];                    // leaky_relu(h @ W_r)
__device__ float g_er[BH * Nn];                         // flat: row R*8+cg
__device__ float g_p [BH * Nn];                         // [b][h][j]
__device__ float g_S [BH * Nn];
__device__ int   g_dummy;
__device__ __nv_bfloat16 g_adjb[(size_t)Bn * Nn * Nn];  // adj as bf16 (exact)
__device__ __nv_bfloat16 g_Bhi[(size_t)Bn * Fn * Nn];   // K-major hi limb of p*Wh
__device__ __nv_bfloat16 g_Blo[(size_t)Bn * Fn * Nn];   // K-major lo limb
__device__ __nv_bfloat16 g_hhi[(size_t)ROWS * Fn];      // h hi limb
__device__ __nv_bfloat16 g_hlo[(size_t)ROWS * Fn];      // h lo limb
__device__ __nv_bfloat16 g_Wthi[Fn * Fn];               // W_r^T hi limb [n][k]
__device__ __nv_bfloat16 g_Wtlo[Fn * Fn];               // W_r^T lo limb

// ---------------------------------------------------------------------------
// Portable PTX helpers
// ---------------------------------------------------------------------------
__device__ __forceinline__ uint32_t smem_u32(const void* p) {
    uint32_t a;
    asm("{ .reg .u64 t; cvta.to.shared.u64 t, %1; cvt.u32.u64 %0, t; }"
        : "=r"(a) : "l"(p));
    return a;
}
#define SWZ(x) ((x) ^ (((x) >> 3) & 0x70))

#define CP_ASYNC16(dst, src) \
    asm volatile("cp.async.cg.shared.global [%0], [%1], 16;" \
                 :: "r"(dst), "l"(src) : "memory")
#define CP_COMMIT() asm volatile("cp.async.commit_group;" ::: "memory")
#define CP_WAIT(n)  asm volatile("cp.async.wait_group %0;" :: "n"(n) : "memory")

__device__ __forceinline__ void ldsm_x4(uint32_t* r, uint32_t addr) {
    asm volatile("ldmatrix.sync.aligned.m8n8.x4.shared.b16 {%0,%1,%2,%3}, [%4];"
                 : "=r"(r[0]), "=r"(r[1]), "=r"(r[2]), "=r"(r[3]) : "r"(addr));
}

__device__ __forceinline__ void mma16816(float* d, const uint32_t* a,
                                         uint32_t b0, uint32_t b1) {
    asm volatile(
        "mma.sync.aligned.m16n8k16.row.col.f32.bf16.bf16.f32 "
        "{%0,%1,%2,%3}, {%4,%5,%6,%7}, {%8,%9}, {%0,%1,%2,%3};"
        : "+f"(d[0]), "+f"(d[1]), "+f"(d[2]), "+f"(d[3])
        : "r"(a[0]), "r"(a[1]), "r"(a[2]), "r"(a[3]), "r"(b0), "r"(b1));
}

// ---------------------------------------------------------------------------
// Kernel F: filler so the profiled launch (#4) is gemm_wh_mma_kernel.
// ---------------------------------------------------------------------------
__global__ void filler_kernel() { if (threadIdx.x == 0) g_dummy = 0; }

// ---------------------------------------------------------------------------
// Kernel 0a: split h into bf16 hi/lo.  8 elems/thread.
// ---------------------------------------------------------------------------
__global__ void hsplit_kernel(const float* __restrict__ h) {
    const size_t idx = (size_t)(blockIdx.x * blockDim.x + threadIdx.x) * 8;
    float4 x0 = *(const float4*)&h[idx];
    float4 x1 = *(const float4*)&h[idx + 4];
    float xs[8] = {x0.x, x0.y, x0.z, x0.w, x1.x, x1.y, x1.z, x1.w};
    __nv_bfloat16 hi[8], lo[8];
#pragma unroll
    for (int i = 0; i < 8; i++) {
        hi[i] = __float2bfloat16(xs[i]);
        lo[i] = __float2bfloat16(xs[i] - __bfloat162float(hi[i]));
    }
    *(uint4*)&g_hhi[idx] = *(uint4*)hi;
    *(uint4*)&g_hlo[idx] = *(uint4*)lo;
}

// ---------------------------------------------------------------------------
// Kernel 0b: W_r^T split.  64x64 tiles, 256 threads.
// ---------------------------------------------------------------------------
__global__ void wtsplit_kernel(const float* __restrict__ W) {
    __shared__ float ts[64][65];
    const int k0 = blockIdx.x * 64;
    const int n0 = blockIdx.y * 64;
    const int t  = threadIdx.x;
#pragma unroll
    for (int it = 0; it < 16; it++) {
        int idx = it * 256 + t;
        int r = idx >> 6, c = idx & 63;
        ts[r][c] = W[(size_t)(k0 + r) * Fn + n0 + c];
    }
    __syncthreads();
#pragma unroll
    for (int it = 0; it < 16; it++) {
        int idx = it * 256 + t;
        int r = idx >> 6, c = idx & 63;
        float x = ts[c][r];
        __nv_bfloat16 hi = __float2bfloat16(x);
        g_Wthi[(size_t)(n0 + r) * Fn + k0 + c] = hi;
        g_Wtlo[(size_t)(n0 + r) * Fn + k0 + c] =
            __float2bfloat16(x - __bfloat162float(hi));
    }
}

// ---------------------------------------------------------------------------
// Kernel 1: Wh = leaky_relu(h @ W_r) via HMMA hi/lo (3 products) + fused er.
// CTA 128x128, 512 threads, 16 warps = 4M x 4N, warp tile 32x32 (acc=32 regs).
// SMEM/stage: Ahi|Alo|Bhi|Blo 16KB each = 64KB; x2 = 128KB.
// ---------------------------------------------------------------------------
#define WH_STG   65536
#define WH_SMEM  (2 * WH_STG)
#define WOFF_AH  0
#define WOFF_AL  16384
#define WOFF_BH  32768
#define WOFF_BL  49152

__global__ void __launch_bounds__(512) gemm_wh_mma_kernel(const float* __restrict__ avec) {
    extern __shared__ __align__(1024) char smem[];
    const uint32_t sb = smem_u32(smem);

    const int t   = threadIdx.x;
    const int wid = t >> 5, lane = t & 31;
    const int i0  = blockIdx.x * 128;   // source rows
    const int n0  = blockIdx.y * 128;   // source cols

    const __nv_bfloat16* gAh = g_hhi + (size_t)i0 * Fn;
    const __nv_bfloat16* gAl = g_hlo + (size_t)i0 * Fn;
    const __nv_bfloat16* gBh = g_Wthi + (size_t)n0 * Fn;
    const __nv_bfloat16* gBl = g_Wtlo + (size_t)n0 * Fn;

    auto load_stage = [&](int slab, int stg) {
        const int k0 = slab * 64;
        const uint32_t base = sb + stg * WH_STG;
#pragma unroll
        for (int it = 0; it < 2; it++) {          // 128 rows x 8 chunks each array
            int c = it * 512 + t;
            int row = c >> 3, chk = c & 7;
            uint32_t doff = SWZ((uint32_t)(row * 128 + chk * 16));
            const size_t goff = (size_t)row * Fn + k0 + chk * 8;
            CP_ASYNC16(base + WOFF_AH + doff, gAh + goff);
            CP_ASYNC16(base + WOFF_AL + doff, gAl + goff);
            CP_ASYNC16(base + WOFF_BH + doff, gBh + goff);
            CP_ASYNC16(base + WOFF_BL + doff, gBl + goff);
        }
    };

    const int wm = wid & 3, wn = wid >> 2;        // 4 x 4 warps
    const int g  = lane >> 2, tg = lane & 3;
    const int lrow = (lane & 7) + ((lane >> 3) & 1) * 8;
    const int lkb  = (lane >> 4) * 16;

    uint32_t a_off[2], b_off[2];
#pragma unroll
    for (int mt = 0; mt < 2; mt++)
        a_off[mt] = (uint32_t)((wm * 32 + mt * 16 + lrow) * 128 + lkb);
#pragma unroll
    for (int nt2 = 0; nt2 < 2; nt2++)
        b_off[nt2] = (uint32_t)((wn * 32 + nt2 * 16 + lrow) * 128 + lkb);

    float acc[2][4][4];
#pragma unroll
    for (int i = 0; i < 2; i++)
#pragma unroll
        for (int j = 0; j < 4; j++)
#pragma unroll
            for (int k = 0; k < 4; k++) acc[i][j][k] = 0.f;

    load_stage(0, 0);
    CP_COMMIT();

    const int NSLAB = Fn / 64;  // 8
    for (int s = 0; s < NSLAB; s++) {
        const int stg = s & 1;
        if (s + 1 < NSLAB) {
            load_stage(s + 1, stg ^ 1);
            CP_COMMIT();
            CP_WAIT(1);
        } else {
            CP_WAIT(0);
        }
        __syncthreads();

        const uint32_t Ah = sb + stg * WH_STG + WOFF_AH;
        const uint32_t Al = sb + stg * WH_STG + WOFF_AL;
        const uint32_t Bh = sb + stg * WH_STG + WOFF_BH;
        const uint32_t Bl = sb + stg * WH_STG + WOFF_BL;

#pragma unroll
        for (int kk = 0; kk < 4; kk++) {
            uint32_t af[2][4], bhf[2][4], blf[2][4];
#pragma unroll
            for (int nt2 = 0; nt2 < 2; nt2++) {
                ldsm_x4(bhf[nt2], Bh + SWZ(b_off[nt2] + kk * 32));
                ldsm_x4(blf[nt2], Bl + SWZ(b_off[nt2] + kk * 32));
            }
#pragma unroll
            for (int mt = 0; mt < 2; mt++)
                ldsm_x4(af[mt], Ah + SWZ(a_off[mt] + kk * 32));
#pragma unroll
            for (int mt = 0; mt < 2; mt++)
#pragma unroll
                for (int nt = 0; nt < 4; nt++) {
                    const int n2 = nt >> 1, hf = nt & 1;
                    mma16816(acc[mt][nt], af[mt], bhf[n2][hf], bhf[n2][hf + 2]);
                    mma16816(acc[mt][nt], af[mt], blf[n2][hf], blf[n2][hf + 2]);
                }
            // A-lo x B-hi
#pragma unroll
            for (int mt = 0; mt < 2; mt++)
                ldsm_x4(af[mt], Al + SWZ(a_off[mt] + kk * 32));
#pragma unroll
            for (int mt = 0; mt < 2; mt++)
#pragma unroll
                for (int nt = 0; nt < 4; nt++) {
                    const int n2 = nt >> 1, hf = nt & 1;
                    mma16816(acc[mt][nt], af[mt], bhf[n2][hf], bhf[n2][hf + 2]);
                }
        }
        __syncthreads();
    }

    // Epilogue: leaky_relu + store + fused er partials
    float a_c0[4], a_c1[4];
#pragma unroll
    for (int nt = 0; nt < 4; nt++) {
        const int c63 = (wn * 32 + tg * 2 + nt * 8) & 63;
        a_c0[nt] = avec[c63];
        a_c1[nt] = avec[c63 + 1];
    }

    float erp[2][2];
    const int cb = n0 + wn * 32 + tg * 2;
#pragma unroll
    for (int mt = 0; mt < 2; mt++) {
        const int r0 = i0 + wm * 32 + mt * 16 + g;
        const int r1 = r0 + 8;
        float e0 = 0.f, e1 = 0.f;
#pragma unroll
        for (int nt = 0; nt < 4; nt++) {
            const int c = cb + nt * 8;
            float x0 = acc[mt][nt][0], x1 = acc[mt][nt][1];
            float x2 = acc[mt][nt][2], x3 = acc[mt][nt][3];
            float2 v0, v1;
            v0.x = x0 > 0.f ? x0 : SLOPE * x0;
            v0.y = x1 > 0.f ? x1 : SLOPE * x1;
            v1.x = x2 > 0.f ? x2 : SLOPE * x2;
            v1.y = x3 > 0.f ? x3 : SLOPE * x3;
            *(float2*)&g_Wh[(size_t)r0 * Fn + c] = v0;
            *(float2*)&g_Wh[(size_t)r1 * Fn + c] = v1;
            e0 += v0.x * a_c0[nt] + v0.y * a_c1[nt];
            e1 += v1.x * a_c0[nt] + v1.y * a_c1[nt];
        }
        erp[mt][0] = e0;
        erp[mt][1] = e1;
    }

    // Reduce er over tg lanes; per 32-col band sums in smem [4 bands][128 rows].
    float* er_sm = (float*)smem;
    __syncthreads();
#pragma unroll
    for (int mt = 0; mt < 2; mt++) {
#pragma unroll
        for (int rr = 0; rr < 2; rr++) {
            float v = erp[mt][rr];
            v += __shfl_xor_sync(0xffffffffu, v, 1);
            v += __shfl_xor_sync(0xffffffffu, v, 2);
            if (tg == 0)
                er_sm[wn * 128 + wm * 32 + mt * 16 + g + rr * 8] = v;
        }
    }
    __syncthreads();
    // Combine two 32-col bands per 64-group.  RAW RESHAPE: flat er row = R*8+cg.
    if (t < 256) {
        const int k = t >> 7, r = t & 127;      // k<2 col groups in this CTA
        const int cg = blockIdx.y * 2 + k;
        const int row = i0 + r;
        g_er[(size_t)row * 8 + cg] =
            er_sm[(2 * k) * 128 + r] + er_sm[(2 * k + 1) * 128 + r];
    }
}

// ---------------------------------------------------------------------------
// Kernel 3: p = exp(er - rowmax) per (b,h).  1024 threads.
// ---------------------------------------------------------------------------
__global__ void __launch_bounds__(1024) maxexp_kernel() {
    __shared__ float sm[32];
    const int bh = blockIdx.x;
    const float* e = g_er + bh * Nn;
    const int t = threadIdx.x;
    float mx = fmaxf(e[t], e[t + 1024]);
#pragma unroll
    for (int o = 16; o; o >>= 1) mx = fmaxf(mx, __shfl_xor_sync(0xffffffffu, mx, o));
    if ((t & 31) == 0) sm[t >> 5] = mx;
    __syncthreads();
    float mall = sm[0];
#pragma unroll
    for (int i = 1; i < 32; i++) mall = fmaxf(mall, sm[i]);
    g_p[bh * Nn + t]        = expf(e[t] - mall);
    g_p[bh * Nn + t + 1024] = expf(e[t + 1024] - mall);
}

// ---------------------------------------------------------------------------
// Kernel 4: FUSED adj->bf16 + S.  8 rows/CTA, p staged in 64KB smem.
// ---------------------------------------------------------------------------
#define ADJS_SMEM (Hn * Nn * 4)   // 64KB

__global__ void __launch_bounds__(256) adjs_kernel(const int* __restrict__ adj) {
    extern __shared__ __align__(16) float ps[];   // [Hn][Nn]
    const int blk = blockIdx.x;
    const int b   = blk >> 8;                // 256 CTAs per batch
    const int r0  = (blk & 255) * 8;
    const int t   = threadIdx.x;

    const float* pb = g_p + (size_t)b * Hn * Nn;
#pragma unroll
    for (int it = 0; it < 16; it++)
        ((float4*)ps)[it * 256 + t] = ((const float4*)pb)[it * 256 + t];
    __syncthreads();

    const int wid = t >> 5, lane = t & 31;
    const int grow = b * Nn + r0 + wid;
    const int* arow = adj + (size_t)grow * Nn;
    __nv_bfloat16* brow = g_adjb + (size_t)grow * Nn;

    float s[Hn] = {};
#pragma unroll 4
    for (int it = 0; it < 16; it++) {
        const int j = (it * 32 + lane) * 4;
        int4 v = *(const int4*)&arow[j];
        float f0 = (float)v.x, f1 = (float)v.y, f2 = (float)v.z, f3 = (float)v.w;
        __nv_bfloat162 c0 = __floats2bfloat162_rn(f0, f1);
        __nv_bfloat162 c1 = __floats2bfloat162_rn(f2, f3);
        uint2 u;
        u.x = *(uint32_t*)&c0;
        u.y = *(uint32_t*)&c1;
        *(uint2*)&brow[j] = u;
#pragma unroll
        for (int hh = 0; hh < Hn; hh++) {
            float4 pv = *(const float4*)&ps[hh * Nn + j];
            s[hh] += f0 * pv.x + f1 * pv.y + f2 * pv.z + f3 * pv.w;
        }
    }
#pragma unroll
    for (int hh = 0; hh < Hn; hh++) {
        float v = s[hh];
#pragma unroll
        for (int o = 16; o; o >>= 1) v += __shfl_down_sync(0xffffffffu, v, o);
        if (lane == 0) g_S[(size_t)b * Hn * Nn + hh * Nn + r0 + wid] = v;
    }
}

// ---------------------------------------------------------------------------
// Kernel 4b: K-major bf16 hi/lo B operand: [b][col=h*64+c][j] = p[j]*Wh[j,c]
// ---------------------------------------------------------------------------
__global__ void bprep_kernel() {
    __shared__ float ts[64][65];
    const int j0 = blockIdx.x * 64;
    const int h  = blockIdx.y;
    const int b  = blockIdx.z;
    const int t  = threadIdx.x;

    const float* Wb = g_Wh + (size_t)(b * Hn + h) * Nn * Dn;
    const float* pb = g_p + (b * Hn + h) * Nn;

#pragma unroll
    for (int it = 0; it < 16; it++) {
        int idx = it * 256 + t;
        int r = idx >> 6, c = idx & 63;
        ts[r][c] = Wb[(size_t)(j0 + r) * Dn + c] * pb[j0 + r];
    }
    __syncthreads();

    __nv_bfloat16* bh = g_Bhi + ((size_t)b * Fn + h * Dn) * Nn;
    __nv_bfloat16* bl = g_Blo + ((size_t)b * Fn + h * Dn) * Nn;
#pragma unroll
    for (int it = 0; it < 16; it++) {
        int idx = it * 256 + t;
        int c = idx >> 6, r = idx & 63;
        float x = ts[r][c];
        __nv_bfloat16 hi = __float2bfloat16(x);
        float lo = x - __bfloat162float(hi);
        bh[(size_t)c * Nn + j0 + r] = hi;
        bl[(size_t)c * Nn + j0 + r] = __float2bfloat16(lo);
    }
}

// ---------------------------------------------------------------------------
// Kernel 5: warp-MMA attention GEMM.
// CTA 128x128, 512 threads, 16 warps = 4M x 4N, warp tile 32x32, 2-stage.
// SMEM/stage: A 16K | Bhi 16K | Blo 16K = 48KB; x2 = 96KB.
// ---------------------------------------------------------------------------
#define STG_BYTES 49152
#define ATT_SMEM  (2 * STG_BYTES)
#define OFF_A  0
#define OFF_BH 16384
#define OFF_BL 32768

__global__ void __launch_bounds__(512) att_mma_kernel(float* __restrict__ out) {
    extern __shared__ __align__(1024) char smem[];
    const uint32_t sb = smem_u32(smem);

    const int t    = threadIdx.x;
    const int wid  = t >> 5, lane = t & 31;
    const int i0   = blockIdx.x * 128;
    const int n0c  = blockIdx.y * 128;
    const int b    = blockIdx.z;

    const __nv_bfloat16* gA  = g_adjb + ((size_t)b * Nn + i0) * Nn;
    const __nv_bfloat16* gBh = g_Bhi + ((size_t)b * Fn + n0c) * Nn;
    const __nv_bfloat16* gBl = g_Blo + ((size_t)b * Fn + n0c) * Nn;

    auto load_stage = [&](int slab, int stg) {
        const int k0 = slab * 64;
        const uint32_t base = sb + stg * STG_BYTES;
#pragma unroll
        for (int it = 0; it < 2; it++) {
            int c = it * 512 + t;
            int row = c >> 3, chk = c & 7;
            uint32_t doff = SWZ((uint32_t)(row * 128 + chk * 16));
            const size_t goff = (size_t)row * Nn + k0 + chk * 8;
            CP_ASYNC16(base + OFF_A + doff, gA + goff);
            CP_ASYNC16(base + OFF_BH + doff, gBh + goff);
            CP_ASYNC16(base + OFF_BL + doff, gBl + goff);
        }
    };

    const int wm = wid & 3, wn = wid >> 2;
    const int g  = lane >> 2, tg = lane & 3;
    const int lrow = (lane & 7) + ((lane >> 3) & 1) * 8;
    const int lkb  = (lane >> 4) * 16;

    uint32_t a_off[2], b_off[2];
#pragma unroll
    for (int mt = 0; mt < 2; mt++)
        a_off[mt] = (uint32_t)((wm * 32 + mt * 16 + lrow) * 128 + lkb);
#pragma unroll
    for (int nt2 = 0; nt2 < 2; nt2++)
        b_off[nt2] = (uint32_t)((wn * 32 + nt2 * 16 + lrow) * 128 + lkb);

    float acc[2][4][4];
#pragma unroll
    for (int i = 0; i < 2; i++)
#pragma unroll
        for (int j = 0; j < 4; j++)
#pragma unroll
            for (int k = 0; k < 4; k++) acc[i][j][k] = 0.f;

    load_stage(0, 0);
    CP_COMMIT();

    const int NSLAB = Nn / 64;  // 32
    for (int s = 0; s < NSLAB; s++) {
        const int stg = s & 1;
        if (s + 1 < NSLAB) {
            load_stage(s + 1, stg ^ 1);
            CP_COMMIT();
            CP_WAIT(1);
        } else {
            CP_WAIT(0);
        }
        __syncthreads();

        const uint32_t Ab = sb + stg * STG_BYTES + OFF_A;
        const uint32_t Bh = sb + stg * STG_BYTES + OFF_BH;
        const uint32_t Bl = sb + stg * STG_BYTES + OFF_BL;

#pragma unroll
        for (int kk = 0; kk < 4; kk++) {
            uint32_t af[2][4], bhf[2][4], blf[2][4];
#pragma unroll
            for (int mt = 0; mt < 2; mt++)
                ldsm_x4(af[mt], Ab + SWZ(a_off[mt] + kk * 32));
#pragma unroll
            for (int nt2 = 0; nt2 < 2; nt2++) {
                ldsm_x4(bhf[nt2], Bh + SWZ(b_off[nt2] + kk * 32));
                ldsm_x4(blf[nt2], Bl + SWZ(b_off[nt2] + kk * 32));
            }
#pragma unroll
            for (int mt = 0; mt < 2; mt++)
#pragma unroll
                for (int nt = 0; nt < 4; nt++) {
                    const int n2 = nt >> 1, hf = nt & 1;
                    mma16816(acc[mt][nt], af[mt], bhf[n2][hf], bhf[n2][hf + 2]);
                    mma16816(acc[mt][nt], af[mt], blf[n2][hf], blf[n2][hf + 2]);
                }
        }
        __syncthreads();
    }

    const int hwarp = (n0c + wn * 32) >> 6;
    const int cbase = ((wn * 32) & 63) + tg * 2;
    const float* Sb = g_S + (size_t)(b * Hn + hwarp) * Nn;
    float* ob = out + (size_t)(b * Hn + hwarp) * Nn * Dn;

#pragma unroll
    for (int mt = 0; mt < 2; mt++) {
        const int r0 = i0 + wm * 32 + mt * 16 + g;
        const int r1 = r0 + 8;
        float s0 = Sb[r0]; if (s0 == 0.f) s0 = 1.f;
        float s1 = Sb[r1]; if (s1 == 0.f) s1 = 1.f;
        const float inv0 = 1.f / s0, inv1 = 1.f / s1;
#pragma unroll
        for (int nt = 0; nt < 4; nt++) {
            const int c = cbase + nt * 8;
            float x0 = acc[mt][nt][0] * inv0;
            float x1 = acc[mt][nt][1] * inv0;
            float x2 = acc[mt][nt][2] * inv1;
            float x3 = acc[mt][nt][3] * inv1;
            float2 v0, v1;
            v0.x = x0 > 0.f ? x0 : expm1f(x0);
            v0.y = x1 > 0.f ? x1 : expm1f(x1);
            v1.x = x2 > 0.f ? x2 : expm1f(x2);
            v1.y = x3 > 0.f ? x3 : expm1f(x3);
            *(float2*)&ob[(size_t)r0 * Dn + c] = v0;
            *(float2*)&ob[(size_t)r1 * Dn + c] = v1;
        }
    }
}

// ---------------------------------------------------------------------------
// Launch.  Inputs: 0=h f32, 1=adj i32, 2=W_l (unused), 3=W_r f32, 4=a f32
// ---------------------------------------------------------------------------
extern "C" void kernel_launch(void* const* d_in, const int* in_sizes, int n_in,
                              void* d_out, int out_size) {
    const float* h   = (const float*)d_in[0];
    const int*   adj = (const int*)  d_in[1];
    const float* W_r = (const float*)d_in[3];
    const float* a   = (const float*)d_in[4];
    float* out = (float*)d_out;

    cudaFuncSetAttribute(att_mma_kernel,
                         cudaFuncAttributeMaxDynamicSharedMemorySize, ATT_SMEM);
    cudaFuncSetAttribute(gemm_wh_mma_kernel,
                         cudaFuncAttributeMaxDynamicSharedMemorySize, WH_SMEM);
    cudaFuncSetAttribute(adjs_kernel,
                         cudaFuncAttributeMaxDynamicSharedMemorySize, ADJS_SMEM);

    // #1 filler (so profiled launch #4 = gemm_wh_mma_kernel)
    filler_kernel<<<1, 32>>>();
    // #2,#3 operand splits
    hsplit_kernel<<<(ROWS * Fn / 8) / 256, 256>>>(h);
    {
        dim3 grid(Fn / 64, Fn / 64);
        wtsplit_kernel<<<grid, 256>>>(W_r);
    }
    // #4 Wh = leaky_relu(h @ W_r) + fused er
    {
        dim3 grid(ROWS / 128, Fn / 128);
        gemm_wh_mma_kernel<<<grid, 512, WH_SMEM>>>(a);
    }
    // #5 p = exp(er - max)
    maxexp_kernel<<<BH, 1024>>>();
    // #6 fused adj->bf16 + S (smem p)
    adjs_kernel<<<ROWS / 8, 256, ADJS_SMEM>>>(adj);
    // #7 B operand hi/lo
    {
        dim3 grid(Nn / 64, Hn, Bn);
        bprep_kernel<<<grid, 256>>>();
    }
    // #8 out = elu(D^-1 Adj @ (p .* Wh))
    {
        dim3 grid(Nn / 128, Fn / 128, Bn);
        att_mma_kernel<<<grid, 512, ATT_SMEM>>>(out);
    }
}